// round 12
// baseline (speedup 1.0000x reference)
#include <cuda_runtime.h>
#include <math.h>

// ---------------------------------------------------------------------------
// Quantum circuit collapsed analytically (see R1-R11).
// R12: 2 warps per batch element (512 amps each) for occupancy.
//   - qubit 0 (warp-crossing bit, p bit 9) folded into init: each warp
//     computes own AND partner init phases (closed-form delta) and applies
//     the tangent stage locally -> no mid-pipeline exchange.
//   - qubit 1 scalar stage (mask 15), qubits 2-4 packed (masks 7,3,1),
//     qubits 5-9 via 64-bit shfl_xor.
//   - output pairs (k, k^768) cross warps: warp1 stores final state to smem,
//     one __syncthreads, warp0 reduces.
// Slot algebra: warp bit w = p bit 9 (r bit 4); reg rho4 holds r4=gray4(rho4);
//   E walk: single flip at ctz(rho4), signs = gray4(rho4) bits.
//   H walk: signs = rho4^(rho4>>2) (bit3 term warp-adjusted), flips {bb,bb-1}.
// ---------------------------------------------------------------------------

#define NQ 10
#define NT 256          // 8 warps = 4 batch elements per block
#define NBLK 64
typedef unsigned long long u64;

#define F2PACK(d, lo, hi) asm("mov.b64 %0, {%1, %2};" : "=l"(d) : "f"(lo), "f"(hi))
#define F2UNPACK(lo, hi, s) asm("mov.b64 {%0, %1}, %2;" : "=f"(lo), "=f"(hi) : "l"(s))
#define F2FMA(d, a, b, c) asm("fma.rn.f32x2 %0, %1, %2, %3;" : "=l"(d) : "l"(a), "l"(b), "l"(c))

__device__ __forceinline__ u64 f2bcast(float v) { u64 d; F2PACK(d, v, v); return d; }
__device__ __forceinline__ u64 f2fma(u64 a, u64 b, u64 c) { u64 d; F2FMA(d, a, b, c); return d; }

// compile-time-foldable count-trailing-zeros (device-safe)
__host__ __device__ __forceinline__ constexpr int ctz5(int v) {
    return (v & 1) ? 0 : (v & 2) ? 1 : (v & 4) ? 2 : (v & 8) ? 3 : 4;
}

// exp(i*pi*A): exact mod-2 reduction, then MUFU sin/cos on |arg| <= pi
__device__ __forceinline__ void sincospi_fast(float A, float* sn, float* cs) {
    float a = fmaf(-2.0f, rintf(0.5f * A), A);   // a in [-1, 1]
    __sincosf(a * 3.14159274101257324f, sn, cs); // MUFU.SIN / MUFU.COS
}

__device__ int   g_flagv[NBLK];
__device__ float g_t[NQ];          // tan(pi*wx) per qubit
__device__ float g_ccoef, g_scoef; // output coefs incl. C^2/1024
__device__ float g_zloE[32];       // Z_low[lane] + Z_high[r=0] (all-minus)
__device__ float g_wzh2[5];        // 2*wz[qubit 4-b] for r-bit b

// One prologue: per-block flag partials + (block 0) gate prep.
__global__ __launch_bounds__(256) void k_pre(const float* __restrict__ in, int n,
                                             const float* __restrict__ w) {
    const int t = threadIdx.x;
    int p = 0;
    const int n4 = n >> 2;
    const float4* in4 = (const float4*)in;
    for (int i = blockIdx.x * 256 + t; i < n4; i += NBLK * 256) {
        float4 v = in4[i];
        p |= (v.x > 1.0f) | (v.y > 1.0f) | (v.z > 1.0f) | (v.w > 1.0f);
    }
    for (int i = (n4 << 2) + blockIdx.x * 256 + t; i < n; i += NBLK * 256)
        p |= (in[i] > 1.0f);
    int f = __syncthreads_or(p);
    if (t == 0) g_flagv[blockIdx.x] = f;

    if (blockIdx.x == 0) {
        if (t == 0) {
            float csq = 1.0f;
            #pragma unroll
            for (int q = 0; q < NQ; q++) {
                float sx, cx;
                sincospif(w[3 + q], &sx, &cx);      // Rx half-angle = pi*wx
                g_t[q] = sx / cx;
                csq *= cx * cx;
            }
            float s, c;
            sincospif(2.0f * (w[0] + w[1] + w[2]), &s, &c);
            const float k = csq * (1.0f / 1024.0f);
            g_ccoef = c * k;
            g_scoef = 2.0f * s * k;
            #pragma unroll
            for (int b = 0; b < 5; b++)
                g_wzh2[b] = 2.0f * w[3 + NQ + 4 - b]; // qubit 4-b <-> r-bit b
        }
        if (t < 32) {
            float zlo = 0.0f, zh0 = 0.0f;
            #pragma unroll
            for (int i = 0; i < 5; i++) {
                float wl = w[3 + NQ + 9 - i];       // qubits 9..5 (p bits 0..4)
                zlo += ((t >> i) & 1) ? wl : -wl;
                zh0 -= w[3 + NQ + i];               // Z_high at r=0: all minus
            }
            g_zloE[t] = zlo + zh0;
        }
    }
}

__global__ __launch_bounds__(NT, 4) void k_main(const float* __restrict__ in,
                                                float* __restrict__ out, int batch) {
    __shared__ float2 sm[NT / 64][16][32];   // warp1 final state per element

    const int warp = threadIdx.x >> 5;
    const int lane = threadIdx.x & 31;
    const int w = warp & 1;                  // p bit 9 (r bit 4)
    const int e = warp >> 1;                 // element within block
    int b = blockIdx.x * (NT / 64) + e;
    if (b >= batch) b = batch - 1;           // clamp (keep block convergent)

    // --- flag from per-block partials (two per lane) ---
    int fp = g_flagv[lane] | g_flagv[lane + 32];
    const int flag = __any_sync(0xFFFFFFFFu, fp != 0);

    // --- load + transform features ---
    float x[NQ];
    #pragma unroll
    for (int q = 0; q < NQ; q++) x[q] = __ldg(&in[b * NQ + q]);
    if (flag) {
        #pragma unroll
        for (int q = 0; q < NQ; q++) x[q] = atanf(x[q]);
    }
    float Q = 0.0f;
    #pragma unroll
    for (int q = 0; q < NQ; q++) Q += x[q] * x[q];

    // --- lane-side terms (p bits 0..4) ---
    const int gl = lane ^ (lane >> 1);
    float Lbase = 0.0f;
    #pragma unroll
    for (int i = 0; i < 5; i++)
        Lbase += ((gl >> i) & 1) ? x[9 - i] : -x[9 - i];
    const float Lflip = Lbase - 2.0f * (((gl >> 4) & 1) ? x[5] : -x[5]);

    // --- warp-side constants ---
    const float wsign = 1.0f - 2.0f * (float)w;
    float wzh2[4], hx[4];
    #pragma unroll
    for (int i = 0; i < 4; i++) wzh2[i] = g_wzh2[i];
    hx[0] = 2.0f * x[4];
    hx[1] = 2.0f * x[3];
    hx[2] = 2.0f * x[2];
    hx[3] = wsign * 2.0f * x[1];             // bit-3 term absorbs w
    const float wz0_2 = g_wzh2[4];           // 2*wz[qubit 0]
    const float hw4   = wsign * 2.0f * x[0];
    const float dE    = wsign * wz0_2;       // partner E delta
    const float E0w   = fmaf(-0.5f, Q, g_zloE[lane]) + (w ? wz0_2 : 0.0f);
    const float H0    = -(x[2] + x[3] + x[4]) - 0.5f * hx[3] - 0.5f * hw4;

    // --- init: own amp + partner amp, fold qubit-0 stage (no comm) ---
    const float t0 = g_t[0];
    float X[16], Y[16];
    {
        float H = H0, E = E0w;
        #pragma unroll
        for (int rho4 = 0; rho4 < 16; rho4++) {
            if (rho4) {
                const int bb = ctz5(rho4);                    // compile-time
                const int eb = ((rho4 ^ (rho4 >> 1)) >> bb) & 1;
                E = eb ? (E + wzh2[bb]) : (E - wzh2[bb]);
                const int sg = rho4 ^ (rho4 >> 2);
                const int hb = (sg >> bb) & 1;
                H = hb ? (H + hx[bb]) : (H - hx[bb]);
                if (bb >= 1) {
                    const int hb2 = (sg >> (bb - 1)) & 1;
                    H = hb2 ? (H + hx[bb - 1]) : (H - hx[bb - 1]);
                }
            }
            const int sg3 = ((rho4 ^ (rho4 >> 2)) >> 3) & 1;  // compile-time
            const float L  = ((rho4 ^ (rho4 >> 1)) & 1) ? Lflip : Lbase;
            const float S0 = H + L;
            const float A0 = fmaf(0.5f * S0, S0, S0 + E);
            const float dS = (sg3 ? -hx[3] : hx[3]) + hw4;
            const float S1 = S0 + dS;
            const float A1 = fmaf(0.5f * S1, S1, S1 + (E + dE));
            float x0, y0, x1, y1;
            sincospi_fast(A0, &y0, &x0);
            sincospi_fast(A1, &y1, &x1);
            X[rho4] = fmaf( t0, y1, x0);     // qubit-0 tangent stage
            Y[rho4] = fmaf(-t0, x1, y0);
        }
    }

    // --- qubit 1: crossed stage, mask 15 (scalar, pre-pack) ---
    {
        const float t1 = g_t[1];
        #pragma unroll
        for (int a = 0; a < 8; a++) {
            const int c = 15 - a;                    // a ^ 15
            float xa = X[a], ya = Y[a], xc = X[c], yc = Y[c];
            X[a] = fmaf( t1, yc, xa);
            Y[a] = fmaf(-t1, xc, ya);
            X[c] = fmaf( t1, ya, xc);
            Y[c] = fmaf(-t1, xa, yc);
        }
    }

    // --- pack over rho4-bit3: X2[t] = (X[t], X[t+8]) ---
    u64 X2[8], Y2[8];
    #pragma unroll
    for (int t = 0; t < 8; t++) {
        F2PACK(X2[t], X[t], X[t + 8]);
        F2PACK(Y2[t], Y[t], Y[t + 8]);
    }

    // --- qubits 2..4: packed register stages, masks 7,3,1 ---
    #pragma unroll
    for (int q = 2; q < 5; q++) {
        const int j  = 4 - q;                        // r4-bit index (2,1,0)
        const int mu = (2 << j) - 1;                 // 7,3,1
        const u64 t2  = f2bcast(g_t[q]);
        const u64 nt2 = f2bcast(-g_t[q]);
        #pragma unroll
        for (int t = 0; t < 8; t++) {
            if (t & (1 << j)) continue;              // each pair once
            const int u = t ^ mu;
            u64 xa = X2[t], ya = Y2[t], xb = X2[u], yb = Y2[u];
            X2[t] = f2fma(t2,  yb, xa);
            Y2[t] = f2fma(nt2, xb, ya);
            X2[u] = f2fma(t2,  ya, xb);
            Y2[u] = f2fma(nt2, xa, yb);
        }
    }

    // --- qubits 5..9: lane-bit butterflies via 64-bit shfl_xor ---
    #pragma unroll
    for (int q = 5; q < 10; q++) {
        const int m = 1 << (9 - q);
        const u64 t2  = f2bcast(g_t[q]);
        const u64 nt2 = f2bcast(-g_t[q]);
        #pragma unroll
        for (int k = 0; k < 8; k++) {
            u64 oy = __shfl_xor_sync(0xFFFFFFFFu, Y2[k], m);
            u64 ox = __shfl_xor_sync(0xFFFFFFFFu, X2[k], m);
            X2[k] = f2fma(t2,  oy, X2[k]);
            Y2[k] = f2fma(nt2, ox, Y2[k]);
        }
    }

    // --- output: pairs (k, k^768) = (w0: rho4) <-> (w1: rho4^15), same lane ---
    if (w == 1) {
        #pragma unroll
        for (int t = 0; t < 8; t++) {
            float xl, xh, yl, yh;
            F2UNPACK(xl, xh, X2[t]);
            F2UNPACK(yl, yh, Y2[t]);
            sm[e][t][lane]     = make_float2(xl, yl);
            sm[e][t + 8][lane] = make_float2(xh, yh);
        }
    }
    __syncthreads();
    if (w == 0) {
        const float cc = g_ccoef, sc = g_scoef;
        float acc = 0.0f;
        #pragma unroll
        for (int t = 0; t < 8; t++) {
            float xl, xh, yl, yh;
            F2UNPACK(xl, xh, X2[t]);
            F2UNPACK(yl, yh, Y2[t]);
            float2 pa = sm[e][15 - t][lane];         // partner of rho4 = t
            float2 pb = sm[e][7 - t][lane];          // partner of rho4 = t+8
            acc += cc * ((pa.x * pa.x + pa.y * pa.y) - (xl * xl + yl * yl))
                 + sc * (xl * pa.x + yl * pa.y);
            acc += cc * ((pb.x * pb.x + pb.y * pb.y) - (xh * xh + yh * yh))
                 + sc * (xh * pb.x + yh * pb.y);
        }
        #pragma unroll
        for (int o = 16; o; o >>= 1) acc += __shfl_xor_sync(0xFFFFFFFFu, acc, o);
        if (lane == 0) out[b] = acc;
    }
}

extern "C" void kernel_launch(void* const* d_in, const int* in_sizes, int n_in,
                              void* d_out, int out_size) {
    const float* inputs = (const float*)d_in[0];   // [8192, 10]
    const float* weight = (const float*)d_in[1];   // [23]
    // d_in[2] = entangle_matrix: fixed CNOT cascade, replaced by closed-form perm
    float* out = (float*)d_out;                    // [8192]

    const int batch = in_sizes[0] / NQ;
    const int n_elems = in_sizes[0];

    k_pre<<<NBLK, 256>>>(inputs, n_elems, weight);
    k_main<<<(batch + (NT / 64) - 1) / (NT / 64), NT>>>(inputs, out, batch);
}

// round 13
// speedup vs baseline: 1.2778x; 1.2778x over previous
#include <cuda_runtime.h>
#include <math.h>

// ---------------------------------------------------------------------------
// Quantum circuit collapsed analytically (see R1-R11).
// R13 = R11 k_main (best: 1 warp/element, Gray register layout, tangent
// butterflies, MUFU sincos) + PDL overlap of k_pre with k_main's prelude:
//   k_pre:  griddepcontrol.launch_dependents at end
//   k_main: feature LDGs first, griddepcontrol.wait before reading k_pre data
// ---------------------------------------------------------------------------

#define NQ 10
#define NT 256          // 8 warps = 8 batch elements per block
#define NBLK 64
typedef unsigned long long u64;

#define F2PACK(d, lo, hi) asm("mov.b64 %0, {%1, %2};" : "=l"(d) : "f"(lo), "f"(hi))
#define F2UNPACK(lo, hi, s) asm("mov.b64 {%0, %1}, %2;" : "=f"(lo), "=f"(hi) : "l"(s))
#define F2FMA(d, a, b, c) asm("fma.rn.f32x2 %0, %1, %2, %3;" : "=l"(d) : "l"(a), "l"(b), "l"(c))
#define F2MUL(d, a, b)    asm("mul.rn.f32x2 %0, %1, %2;"     : "=l"(d) : "l"(a), "l"(b))
#define F2ADD(d, a, b)    asm("add.rn.f32x2 %0, %1, %2;"     : "=l"(d) : "l"(a), "l"(b))

__device__ __forceinline__ u64 f2bcast(float v) { u64 d; F2PACK(d, v, v); return d; }
__device__ __forceinline__ u64 f2fma(u64 a, u64 b, u64 c) { u64 d; F2FMA(d, a, b, c); return d; }
__device__ __forceinline__ u64 f2mul(u64 a, u64 b) { u64 d; F2MUL(d, a, b); return d; }
__device__ __forceinline__ u64 f2add(u64 a, u64 b) { u64 d; F2ADD(d, a, b); return d; }

// compile-time-foldable count-trailing-zeros (device-safe)
__host__ __device__ __forceinline__ constexpr int ctz5(int v) {
    return (v & 1) ? 0 : (v & 2) ? 1 : (v & 4) ? 2 : (v & 8) ? 3 : 4;
}

// exp(i*pi*A): exact mod-2 reduction, then MUFU sin/cos on |arg| <= pi
__device__ __forceinline__ void sincospi_fast(float A, float* sn, float* cs) {
    float a = fmaf(-2.0f, rintf(0.5f * A), A);   // a in [-1, 1]
    __sincosf(a * 3.14159274101257324f, sn, cs); // MUFU.SIN / MUFU.COS
}

__device__ int   g_flagv[NBLK];
__device__ float g_t[NQ];          // tan(pi*wx) per qubit
__device__ float g_ccoef, g_scoef; // output coefs incl. C^2/1024
__device__ float g_zloE[32];       // Z_low[lane] + Z_high[r=0]
__device__ float g_wzh2[5];        // 2*wz for high-qubit gray walk

// One prologue: per-block flag partials + (block 0) gate prep.
__global__ __launch_bounds__(256) void k_pre(const float* __restrict__ in, int n,
                                             const float* __restrict__ w) {
    const int t = threadIdx.x;
    int p = 0;
    const int n4 = n >> 2;
    const float4* in4 = (const float4*)in;
    for (int i = blockIdx.x * 256 + t; i < n4; i += NBLK * 256) {
        float4 v = in4[i];
        p |= (v.x > 1.0f) | (v.y > 1.0f) | (v.z > 1.0f) | (v.w > 1.0f);
    }
    for (int i = (n4 << 2) + blockIdx.x * 256 + t; i < n; i += NBLK * 256)
        p |= (in[i] > 1.0f);
    int f = __syncthreads_or(p);
    if (t == 0) g_flagv[blockIdx.x] = f;

    if (blockIdx.x == 0) {
        if (t == 0) {
            float csq = 1.0f;
            #pragma unroll
            for (int q = 0; q < NQ; q++) {
                float sx, cx;
                sincospif(w[3 + q], &sx, &cx);      // Rx half-angle = pi*wx
                g_t[q] = sx / cx;
                csq *= cx * cx;
            }
            float s, c;
            sincospif(2.0f * (w[0] + w[1] + w[2]), &s, &c);
            const float k = csq * (1.0f / 1024.0f);
            g_ccoef = c * k;
            g_scoef = 2.0f * s * k;
            #pragma unroll
            for (int b = 0; b < 5; b++)
                g_wzh2[b] = 2.0f * w[3 + NQ + 4 - b]; // qubit 4-b <-> r-bit b
        }
        if (t < 32) {
            float zlo = 0.0f, zh0 = 0.0f;
            #pragma unroll
            for (int i = 0; i < 5; i++) {
                float wl = w[3 + NQ + 9 - i];       // qubits 9..5 (p bits 0..4)
                zlo += ((t >> i) & 1) ? wl : -wl;
                zh0 -= w[3 + NQ + i];               // Z_high at r=0: all minus
            }
            g_zloE[t] = zlo + zh0;
        }
    }
    // PDL: all writes done -> release dependent grid
    asm volatile("griddepcontrol.launch_dependents;");
}

__global__ __launch_bounds__(NT) void k_main(const float* __restrict__ in,
                                             float* __restrict__ out, int batch) {
    const int warp = threadIdx.x >> 5;
    const int lane = threadIdx.x & 31;
    const int b = blockIdx.x * (NT / 32) + warp;
    if (b >= batch) return;

    // --- feature loads first: independent of k_pre (overlaps under PDL) ---
    float x[NQ];
    #pragma unroll
    for (int q = 0; q < NQ; q++) x[q] = __ldg(&in[b * NQ + q]);

    // PDL: wait for k_pre before touching its outputs
    asm volatile("griddepcontrol.wait;" ::: "memory");

    // --- flag from per-block partials (two per lane) ---
    int fp = g_flagv[lane] | g_flagv[lane + 32];
    const int flag = __any_sync(0xFFFFFFFFu, fp != 0);

    if (flag) {
        #pragma unroll
        for (int q = 0; q < NQ; q++) x[q] = atanf(x[q]);
    }
    float Q = 0.0f;
    #pragma unroll
    for (int q = 0; q < NQ; q++) Q += x[q] * x[q];

    // --- lane-side terms ---
    const int gl = lane ^ (lane >> 1);
    float Lbase = 0.0f;
    #pragma unroll
    for (int i = 0; i < 5; i++)
        Lbase += ((gl >> i) & 1) ? x[9 - i] : -x[9 - i];
    const float Lflip = Lbase - 2.0f * (((gl >> 4) & 1) ? x[5] : -x[5]);
    const float E0 = fmaf(-0.5f, Q, g_zloE[lane]);   // dlane + Zh[r=0]

    float wzh2[5], xh2[5];
    #pragma unroll
    for (int i = 0; i < 5; i++) {
        wzh2[i] = g_wzh2[i];
        xh2[i]  = 2.0f * x[4 - i];                   // qubit 4-b <-> r-bit b
    }

    // --- init: scalar amps X[rho],Y[rho], slot r = gray(rho), via walks ---
    float X[32], Y[32];
    {
        float H = -(x[0] + x[1] + x[2] + x[3] + x[4]);
        float E = E0;
        #pragma unroll
        for (int rho = 0; rho < 32; rho++) {
            if (rho) {
                const int bb = ctz5(rho);                    // compile-time
                // E walk: signs = gray(rho) bits, single flip at bb
                const int eb = ((rho ^ (rho >> 1)) >> bb) & 1;
                E = eb ? (E + wzh2[bb]) : (E - wzh2[bb]);
                // H walk: signs = rho ^ (rho>>2), flips at bb and bb-1
                const int sg = rho ^ (rho >> 2);
                const int hb = (sg >> bb) & 1;
                H = hb ? (H + xh2[bb]) : (H - xh2[bb]);
                if (bb >= 1) {
                    const int hb2 = (sg >> (bb - 1)) & 1;
                    H = hb2 ? (H + xh2[bb - 1]) : (H - xh2[bb - 1]);
                }
            }
            const float L = ((rho ^ (rho >> 1)) & 1) ? Lflip : Lbase;
            float S = H + L;
            float A = fmaf(0.5f * S, S, S + E);
            sincospi_fast(A, &Y[rho], &X[rho]);
        }
    }

    // --- qubit 0: crossed stage, storage mask 31 (scalar, pre-pack) ---
    {
        const float t0 = g_t[0];
        #pragma unroll
        for (int a = 0; a < 16; a++) {
            const int c = 31 - a;                    // a ^ 31
            float xa = X[a], ya = Y[a], xc = X[c], yc = Y[c];
            X[a] = fmaf( t0, yc, xa);
            Y[a] = fmaf(-t0, xc, ya);
            X[c] = fmaf( t0, ya, xc);
            Y[c] = fmaf(-t0, xa, yc);
        }
    }

    // --- pack over rho-bit4: X2[t] = (X[t], X[t+16]) ---
    u64 X2[16], Y2[16];
    #pragma unroll
    for (int t = 0; t < 16; t++) {
        F2PACK(X2[t], X[t], X[t + 16]);
        F2PACK(Y2[t], Y[t], Y[t + 16]);
    }

    // --- qubits 1..4: packed register stages, masks 15,7,3,1 ---
    #pragma unroll
    for (int q = 1; q < 5; q++) {
        const int i  = 4 - q;                        // r-bit index
        const int mu = (2 << i) - 1;                 // 15,7,3,1
        const u64 t2  = f2bcast(g_t[q]);
        const u64 nt2 = f2bcast(-g_t[q]);
        #pragma unroll
        for (int t = 0; t < 16; t++) {
            if (t & (1 << i)) continue;              // each pair once
            const int u = t ^ mu;
            u64 xa = X2[t], ya = Y2[t], xb = X2[u], yb = Y2[u];
            X2[t] = f2fma(t2,  yb, xa);
            Y2[t] = f2fma(nt2, xb, ya);
            X2[u] = f2fma(t2,  ya, xb);
            Y2[u] = f2fma(nt2, xa, yb);
        }
    }

    // --- qubits 5..9: lane-bit butterflies via 64-bit shfl_xor ---
    #pragma unroll
    for (int q = 5; q < 10; q++) {
        const int m = 1 << (9 - q);
        const u64 t2  = f2bcast(g_t[q]);
        const u64 nt2 = f2bcast(-g_t[q]);
        #pragma unroll
        for (int k = 0; k < 16; k++) {
            u64 oy = __shfl_xor_sync(0xFFFFFFFFu, Y2[k], m);
            u64 ox = __shfl_xor_sync(0xFFFFFFFFu, X2[k], m);
            X2[k] = f2fma(t2,  oy, X2[k]);
            Y2[k] = f2fma(nt2, ox, Y2[k]);
        }
    }

    // --- output: pairs are the two halves of each pack (mask rho^16) ---
    u64 accP = f2bcast(0.0f);
    float d = 0.0f;
    #pragma unroll
    for (int t = 0; t < 16; t++) {
        u64 P = f2fma(X2[t], X2[t], f2mul(Y2[t], Y2[t]));  // (|w0|^2, |w1|^2)
        accP = f2add(accP, P);
        float xl, xh, yl, yh;
        F2UNPACK(xl, xh, X2[t]);
        F2UNPACK(yl, yh, Y2[t]);
        d = fmaf(xl, xh, d);
        d = fmaf(yl, yh, d);
    }
    float A0, A1;
    F2UNPACK(A0, A1, accP);
    float acc = fmaf(g_ccoef, A1 - A0, g_scoef * d);
    #pragma unroll
    for (int o = 16; o; o >>= 1) acc += __shfl_xor_sync(0xFFFFFFFFu, acc, o);
    if (lane == 0) out[b] = acc;
}

extern "C" void kernel_launch(void* const* d_in, const int* in_sizes, int n_in,
                              void* d_out, int out_size) {
    const float* inputs = (const float*)d_in[0];   // [8192, 10]
    const float* weight = (const float*)d_in[1];   // [23]
    // d_in[2] = entangle_matrix: fixed CNOT cascade, replaced by closed-form perm
    float* out = (float*)d_out;                    // [8192]

    const int batch = in_sizes[0] / NQ;
    const int n_elems = in_sizes[0];

    k_pre<<<NBLK, 256>>>(inputs, n_elems, weight);

    // PDL launch of k_main: overlaps with k_pre; k_main gates itself via
    // griddepcontrol.wait before consuming k_pre outputs.
    cudaLaunchConfig_t cfg = {};
    cfg.gridDim  = dim3((batch + (NT / 32) - 1) / (NT / 32));
    cfg.blockDim = dim3(NT);
    cfg.dynamicSmemBytes = 0;
    cfg.stream = 0;
    cudaLaunchAttribute attr[1];
    attr[0].id = cudaLaunchAttributeProgrammaticStreamSerialization;
    attr[0].val.programmaticStreamSerializationAllowed = 1;
    cfg.attrs = attr;
    cfg.numAttrs = 1;
    cudaError_t err = cudaLaunchKernelEx(&cfg, k_main, inputs, out, batch);
    if (err != cudaSuccess) {
        (void)cudaGetLastError();   // clear; fall back to plain launch
        k_main<<<(batch + (NT / 32) - 1) / (NT / 32), NT>>>(inputs, out, batch);
    }
}